// round 13
// baseline (speedup 1.0000x reference)
#include <cuda_runtime.h>

// Problem constants
#define T_STEPS 1024
#define BATCH   128
#define FEAT    64
#define HID     256
#define KDIM    (HID + FEAT)   // 320
#define NCTA    128
#define TPB     512
#define GQ      32             // batch per group (4 groups)
#define JH      8              // h-columns per CTA
#define KHG     32             // h k's per GEMM warp (8 warps * 32 = 256)
#define KXE     8              // x k's per EPI warp  (8 warps * 8 = 64)
#define TF      (T_STEPS * FEAT)
#define SB      (HID * BATCH)

// ---------------- device scratch ----------------
__device__ float g_xT[T_STEPS * FEAT * BATCH];   // 32MB: xT[t][f][b]
__device__ float g_S[2 * SB];                    // double-buffered h, k-major
__device__ volatile unsigned g_flags[NCTA];
__device__ unsigned g_done;

typedef unsigned long long ull;

#define FMA2(D, S, W) asm("fma.rn.f32x2 %0, %1, %2, %0;" : "+l"(D) : "l"(S), "l"(W))

__device__ __forceinline__ float4 ldcg128v(const float* p) {
    float4 v;
    asm volatile("ld.global.cg.v4.f32 {%0,%1,%2,%3}, [%4];"
                 : "=f"(v.x), "=f"(v.y), "=f"(v.z), "=f"(v.w) : "l"(p));
    return v;
}
__device__ __forceinline__ void stcg32(float* p, float v) {
    asm volatile("st.global.cg.f32 [%0], %1;" :: "l"(p), "f"(v) : "memory");
}

__device__ __forceinline__ float sigf(float x)  { return 1.f / (1.f + __expf(-x)); }
__device__ __forceinline__ float tanhff(float x){ return 2.f / (1.f + __expf(-2.f * x)) - 1.f; }

// ---------------- input transpose: ts[b][t][f] -> xT[t][f][b] ----------------
__global__ void transpose_x_kernel(const float* __restrict__ ts) {
    __shared__ float tile[FEAT * 129];
    int t = blockIdx.x;
    for (int i = threadIdx.x; i < BATCH * FEAT; i += 256) {
        int b = i >> 6, f = i & 63;
        tile[f * 129 + b] = ts[b * TF + t * FEAT + f];
    }
    __syncthreads();
    for (int i = threadIdx.x; i < BATCH * FEAT; i += 256) {
        int f = i >> 7, b = i & 127;
        g_xT[t * (FEAT * BATCH) + f * BATCH + b] = tile[f * 129 + b];
    }
}

// ---------------- weights: w2dup[k][i][rg] duplicated pairs (conflict-free LDS.128) ----------------
__device__ __forceinline__ void load_weights(const float* __restrict__ Whh,
                                             const float* __restrict__ Wih,
                                             const float* __restrict__ bias,
                                             float* w2dup, float* bias_s, int j0) {
    for (int idx = threadIdx.x; idx < KDIM * 32; idx += TPB) {
        int k = idx >> 5, r = idx & 31;
        int jj = r >> 2, gate = r & 3;
        int rg = r >> 3, i = (r & 7) >> 1, lo = r & 1;
        int rgrow = gate * HID + j0 + jj;
        float v = (k < HID) ? Whh[rgrow * HID + k] : Wih[rgrow * FEAT + (k - HID)];
        w2dup[k * 64 + i * 16 + rg * 4 + lo * 2 + 0] = v;
        w2dup[k * 64 + i * 16 + rg * 4 + lo * 2 + 1] = v;
    }
    if (threadIdx.x < 32) {
        int r = threadIdx.x;
        int jj = r >> 2, gate = r & 3;
        bias_s[r] = bias[gate * HID + j0 + jj];
    }
}

// ---------------- one k contribution: 16 FMA2 against 4 LDS.128 ----------------
template <bool OUT>
__device__ __forceinline__ void kstep(float4 s, ull* acc, ull* o,
                                      const float* wk, const float* wo) {
    ulonglong2 ss = *(const ulonglong2*)&s;
#pragma unroll
    for (int i = 0; i < 4; ++i) {
        ulonglong2 w = *(const ulonglong2*)(wk + i * 16);
        FMA2(acc[4 * i + 0], ss.x, w.x); FMA2(acc[4 * i + 1], ss.y, w.x);
        FMA2(acc[4 * i + 2], ss.x, w.y); FMA2(acc[4 * i + 3], ss.y, w.y);
    }
    if (OUT) {
        ulonglong2 w = *(const ulonglong2*)wo;
        FMA2(o[0], ss.x, w.x); FMA2(o[1], ss.y, w.x);
        FMA2(o[2], ss.x, w.y); FMA2(o[3], ss.y, w.y);
    }
}

// ---------------- h-part GEMM over 32 k (critical path) ----------------
template <bool OUT>
__device__ __forceinline__ void gemm_h(const float* __restrict__ sp,
                                       const float* __restrict__ w2dup_rg,
                                       const float* __restrict__ woutd,
                                       ull* acc, ull* o, int klo) {
    float4 sv[8];
#pragma unroll
    for (int i = 0; i < 8; ++i) sv[i] = ldcg128v(sp + (klo + i) * BATCH);
#pragma unroll
    for (int i = 0; i < 24; ++i) {
        float4 s = sv[i & 7];
        sv[i & 7] = ldcg128v(sp + (klo + 8 + i) * BATCH);
        kstep<OUT>(s, acc, o, w2dup_rg + (klo + i) * 64, woutd + (klo + i) * 4);
    }
#pragma unroll
    for (int i = 24; i < 32; ++i)
        kstep<OUT>(sv[i & 7], acc, o, w2dup_rg + (klo + i) * 64, woutd + (klo + i) * 4);
}

// ---------------- x partials over 8 k (EPI warps, off critical path) ----------------
__device__ __forceinline__ void accum_x8(int t, ull* acc, const float* __restrict__ w2dup,
                                         int we, int qb4, int rg4) {
    const float* xp = g_xT + t * (FEAT * BATCH) + qb4;
    const int kx = we * KXE;
    float4 sv[KXE];
#pragma unroll
    for (int i = 0; i < KXE; ++i) sv[i] = ldcg128v(xp + (kx + i) * BATCH);
#pragma unroll
    for (int i = 0; i < KXE; ++i)
        kstep<false>(sv[i], acc, (ull*)0, w2dup + (HID + kx + i) * 64 + rg4, (const float*)0);
}

// partial store: rows w*32 + rg*8 + rl, batches bq*4..+3
__device__ __forceinline__ void sts_partials(float* buf, const ull* acc, int w, int rg, int bq) {
#pragma unroll
    for (int rl = 0; rl < 8; ++rl) {
        ulonglong2 v; v.x = acc[rl * 2 + 0]; v.y = acc[rl * 2 + 1];
        *(ulonglong2*)(buf + (w * 32 + rg * 8 + rl) * GQ + bq * 4) = v;
    }
}

// ---------------- SMEM layout (floats) ----------------
//  w2dup  20480 @ 0
//  woutd   1024 @ 20480
//  red    16384 @ 21504   (2 parities * 8 slices * 32 rows * 32 b)
//  xred   16384 @ 37888
//  red_o   1024 @ 54272   (2 parities * 2 f * 8 slices * 32 b)
//  c_s      256 @ 55296
//  bias_s    32 @ 55552
#define SMEM_FLOATS 55584
#define SMEM_BYTES  (SMEM_FLOATS * 4)

__global__ void __launch_bounds__(TPB, 1) lstm_persistent_kernel(
    const float* __restrict__ Wih_e, const float* __restrict__ Whh_e, const float* __restrict__ b_e,
    const float* __restrict__ Wih_d, const float* __restrict__ Whh_d, const float* __restrict__ b_d,
    const float* __restrict__ Wout, const float* __restrict__ bout,
    float* __restrict__ out)
{
    extern __shared__ float sm[];
    float* w2dup  = sm;
    float* woutd  = sm + 20480;
    float* red    = sm + 21504;
    float* xred   = sm + 37888;
    float* red_o  = sm + 54272;
    float* c_s    = sm + 55296;
    float* bias_s = sm + 55552;

    const int cta   = blockIdx.x;
    const int tid   = threadIdx.x;
    const int grp   = cta >> 5;
    const int slice = cta & 31;
    const int qb0   = grp * GQ;
    const int j0    = slice * JH;
    const int wid   = tid >> 5;
    const int lane  = tid & 31;
    const int rg    = lane >> 3;
    const int bq    = lane & 7;
    const int rg4   = rg * 4;
    const int qb4   = qb0 + bq * 4;
    const int gbase = grp << 5;
    const bool is_gemm = (wid < 8);
    const int ksr   = (wid + slice) & 7;     // gemm k-rotation
    const int klo   = ksr * KHG;
    const int we    = wid - 8;               // epi warp index

    load_weights(Whh_e, Wih_e, b_e, w2dup, bias_s, j0);
    if (tid < 256) {
        int jj = tid >> 5, b = tid & 31;
        stcg32(&g_S[(j0 + jj) * BATCH + qb0 + b], 0.f);
        c_s[jj * GQ + b] = 0.f;
    }
    __syncthreads();
    if (tid == 0) { __threadfence(); g_flags[cta] = 1u; }

    ull acc[16], o[4];
#pragma unroll
    for (int p = 0; p < 16; ++p) acc[p] = 0ull;
    o[0] = o[1] = o[2] = o[3] = 0ull;

    unsigned step = 1u;
    int cur = 0;

    // epi prefill: x-partials for t=0 into xred[step&1 = 1]
    if (!is_gemm) {
        accum_x8(0, acc, w2dup, we, qb4, rg4);
        sts_partials(xred + (step & 1) * 8192, acc, we, rg, bq);
#pragma unroll
        for (int p = 0; p < 16; ++p) acc[p] = 0ull;
    }

    // ================= encoder =================
    for (int t = 0; t < T_STEPS; ++t) {
        int par = step & 1;
        if (is_gemm) {
            if (lane < 5) {
                int idx = (lane < 4) ? (gbase + (klo >> 3) + lane) : cta;
                while (g_flags[idx] < step) { }
            }
            __syncwarp();
            __threadfence();
            gemm_h<false>(g_S + cur * SB + qb4, w2dup + rg4, woutd, acc, o, klo);
            sts_partials(red + par * 8192, acc, wid, rg, bq);
            asm volatile("bar.arrive 2, 512;" ::: "memory");
#pragma unroll
            for (int p = 0; p < 16; ++p) acc[p] = 0ull;
        } else {
            asm volatile("bar.sync 2, 512;" ::: "memory");
            int jj = we, b = lane;
            float gi = bias_s[jj * 4 + 0], gf = bias_s[jj * 4 + 1];
            float gg = bias_s[jj * 4 + 2], go = bias_s[jj * 4 + 3];
            const float* rp = red  + par * 8192;
            const float* xp = xred + par * 8192;
#pragma unroll
            for (int q = 0; q < 8; ++q) {
                const float* ba = rp + (q * 32 + jj * 4) * GQ + b;
                gi += ba[0]; gf += ba[GQ]; gg += ba[2 * GQ]; go += ba[3 * GQ];
            }
#pragma unroll
            for (int q = 0; q < 8; ++q) {
                const float* ba = xp + (q * 32 + jj * 4) * GQ + b;
                gi += ba[0]; gf += ba[GQ]; gg += ba[2 * GQ]; go += ba[3 * GQ];
            }
            float c = sigf(gf) * c_s[jj * GQ + b] + sigf(gi) * tanhff(gg);
            c_s[jj * GQ + b] = c;
            stcg32(&g_S[(cur ^ 1) * SB + (j0 + jj) * BATCH + qb0 + b], sigf(go) * tanhff(c));
            asm volatile("bar.sync 1, 256;" ::: "memory");
            if (tid == 256) { __threadfence(); g_flags[cta] = step + 1u; }
            if (t < T_STEPS - 1) {
                accum_x8(t + 1, acc, w2dup, we, qb4, rg4);
                sts_partials(xred + (par ^ 1) * 8192, acc, we, rg, bq);
#pragma unroll
                for (int p = 0; p < 16; ++p) acc[p] = 0ull;
            }
        }
        ++step;
        cur ^= 1;
    }

    // ================= switch to decoder weights =================
    __syncthreads();
    load_weights(Whh_d, Wih_d, b_d, w2dup, bias_s, j0);
    const int f0 = slice * 2;
    for (int k = tid; k < HID; k += TPB) {
        float v0 = Wout[(f0 + 0) * HID + k];
        float v1 = Wout[(f0 + 1) * HID + k];
        woutd[k * 4 + 0] = v0; woutd[k * 4 + 1] = v0;
        woutd[k * 4 + 2] = v1; woutd[k * 4 + 3] = v1;
    }
    float bo0 = bout[f0], bo1 = bout[f0 + 1];
    __syncthreads();

    if (!is_gemm) { // prefill x(t=1023) with decoder weights into xred[step&1]
        accum_x8(T_STEPS - 1, acc, w2dup, we, qb4, rg4);
        sts_partials(xred + (step & 1) * 8192, acc, we, rg, bq);
#pragma unroll
        for (int p = 0; p < 16; ++p) acc[p] = 0ull;
    }

    // ================= decoder (reversed time) =================
    for (int tt = 0; tt < T_STEPS; ++tt) {
        int t = T_STEPS - 1 - tt;
        int par = step & 1;
        if (is_gemm) {
            if (lane < 5) {
                int idx = (lane < 4) ? (gbase + (klo >> 3) + lane) : cta;
                while (g_flags[idx] < step) { }
            }
            __syncwarp();
            __threadfence();
            gemm_h<true>(g_S + cur * SB + qb4, w2dup + rg4, woutd, acc, o, klo);
            sts_partials(red + par * 8192, acc, wid, rg, bq);
            if (rg == 0) {
                ulonglong2 v0; v0.x = o[0]; v0.y = o[1];
                ulonglong2 v1; v1.x = o[2]; v1.y = o[3];
                *(ulonglong2*)(red_o + par * 512 + wid * GQ + bq * 4) = v0;
                *(ulonglong2*)(red_o + par * 512 + 256 + wid * GQ + bq * 4) = v1;
            }
            asm volatile("bar.arrive 2, 512;" ::: "memory");
#pragma unroll
            for (int p = 0; p < 16; ++p) acc[p] = 0ull;
            o[0] = o[1] = o[2] = o[3] = 0ull;
        } else {
            asm volatile("bar.sync 2, 512;" ::: "memory");
            int jj = we, b = lane;
            float gi = bias_s[jj * 4 + 0], gf = bias_s[jj * 4 + 1];
            float gg = bias_s[jj * 4 + 2], go = bias_s[jj * 4 + 3];
            const float* rp = red  + par * 8192;
            const float* xp = xred + par * 8192;
#pragma unroll
            for (int q = 0; q < 8; ++q) {
                const float* ba = rp + (q * 32 + jj * 4) * GQ + b;
                gi += ba[0]; gf += ba[GQ]; gg += ba[2 * GQ]; go += ba[3 * GQ];
            }
#pragma unroll
            for (int q = 0; q < 8; ++q) {
                const float* ba = xp + (q * 32 + jj * 4) * GQ + b;
                gi += ba[0]; gf += ba[GQ]; gg += ba[2 * GQ]; go += ba[3 * GQ];
            }
            float c = sigf(gf) * c_s[jj * GQ + b] + sigf(gi) * tanhff(gg);
            c_s[jj * GQ + b] = c;
            stcg32(&g_S[(cur ^ 1) * SB + (j0 + jj) * BATCH + qb0 + b], sigf(go) * tanhff(c));
            asm volatile("bar.sync 1, 256;" ::: "memory");
            if (tid == 256) { __threadfence(); g_flags[cta] = step + 1u; }

            if (we == 0) { // output emit for step t (off critical path)
                float s0 = 0.f, s1 = 0.f;
#pragma unroll
                for (int q = 0; q < 8; ++q) {
                    s0 += red_o[par * 512 + q * GQ + b];
                    s1 += red_o[par * 512 + 256 + q * GQ + b];
                }
                float2 res; res.x = s0 + bo0; res.y = s1 + bo1;
                *(float2*)(out + (qb0 + b) * TF + t * FEAT + f0) = res;
            }
            if (tt < T_STEPS - 1) {
                accum_x8(t - 1, acc, w2dup, we, qb4, rg4);
                sts_partials(xred + (par ^ 1) * 8192, acc, we, rg, bq);
#pragma unroll
                for (int p = 0; p < 16; ++p) acc[p] = 0ull;
            }
        }
        ++step;
        cur ^= 1;
    }

    // ---- reset barrier state for graph replays ----
    __syncthreads();
    if (tid == 0) {
        atomicAdd(&g_done, 1u);
        if (cta == 0) {
            while (*((volatile unsigned*)&g_done) < NCTA) { }
            for (int i = 0; i < NCTA; ++i) g_flags[i] = 0u;
            __threadfence();
            g_done = 0u;
        }
    }
}

// ---------------- launch ----------------
extern "C" void kernel_launch(void* const* d_in, const int* in_sizes, int n_in,
                              void* d_out, int out_size) {
    const float* ts    = (const float*)d_in[0];
    const float* Wih_e = (const float*)d_in[1];
    const float* Whh_e = (const float*)d_in[2];
    const float* b_e   = (const float*)d_in[3];
    const float* Wih_d = (const float*)d_in[4];
    const float* Whh_d = (const float*)d_in[5];
    const float* b_d   = (const float*)d_in[6];
    const float* Wout  = (const float*)d_in[7];
    const float* bout  = (const float*)d_in[8];
    float* out = (float*)d_out;

    cudaFuncSetAttribute(lstm_persistent_kernel,
                         cudaFuncAttributeMaxDynamicSharedMemorySize, SMEM_BYTES);

    transpose_x_kernel<<<T_STEPS, 256>>>(ts);
    lstm_persistent_kernel<<<NCTA, TPB, SMEM_BYTES>>>(
        Wih_e, Whh_e, b_e, Wih_d, Whh_d, b_d, Wout, bout, out);
}

// round 14
// speedup vs baseline: 1.8085x; 1.8085x over previous
#include <cuda_runtime.h>

// Problem constants
#define T_STEPS 1024
#define BATCH   128
#define FEAT    64
#define HID     256
#define KDIM    (HID + FEAT)   // 320
#define NCTA    128
#define TPB     512
#define GQ      32             // batch per group (4 groups)
#define JH      8              // h-columns per CTA
#define KHG     32             // h k's per GEMM warp (8 warps * 32 = 256)
#define KXE     8              // x k's per EPI warp  (8 warps * 8 = 64)
#define TF      (T_STEPS * FEAT)
#define SB      (HID * BATCH)

// ---------------- device scratch ----------------
__device__ float g_xT[T_STEPS * FEAT * BATCH];   // 32MB: xT[t][f][b]
__device__ float g_S[2 * SB];                    // double-buffered h, k-major
__device__ volatile unsigned g_flags[NCTA];
__device__ unsigned g_done;

typedef unsigned long long ull;

#define FMA2(D, S, W) asm("fma.rn.f32x2 %0, %1, %2, %0;" : "+l"(D) : "l"(S), "l"(W))

__device__ __forceinline__ float4 ldcg128v(const float* p) {
    float4 v;
    asm volatile("ld.global.cg.v4.f32 {%0,%1,%2,%3}, [%4];"
                 : "=f"(v.x), "=f"(v.y), "=f"(v.z), "=f"(v.w) : "l"(p));
    return v;
}
__device__ __forceinline__ void stcg32(float* p, float v) {
    asm volatile("st.global.cg.f32 [%0], %1;" :: "l"(p), "f"(v) : "memory");
}

__device__ __forceinline__ float sigf(float x)  { return 1.f / (1.f + __expf(-x)); }
__device__ __forceinline__ float tanhff(float x){ return 2.f / (1.f + __expf(-2.f * x)) - 1.f; }

// ---------------- input transpose: ts[b][t][f] -> xT[t][f][b] ----------------
__global__ void transpose_x_kernel(const float* __restrict__ ts) {
    __shared__ float tile[FEAT * 129];
    int t = blockIdx.x;
    for (int i = threadIdx.x; i < BATCH * FEAT; i += 256) {
        int b = i >> 6, f = i & 63;
        tile[f * 129 + b] = ts[b * TF + t * FEAT + f];
    }
    __syncthreads();
    for (int i = threadIdx.x; i < BATCH * FEAT; i += 256) {
        int f = i >> 7, b = i & 127;
        g_xT[t * (FEAT * BATCH) + f * BATCH + b] = tile[f * 129 + b];
    }
}

// ---------------- weights: w2dup[k][i][rg] duplicated pairs (conflict-free LDS.128) ----------------
__device__ __forceinline__ void load_weights(const float* __restrict__ Whh,
                                             const float* __restrict__ Wih,
                                             const float* __restrict__ bias,
                                             float* w2dup, float* bias_s, int j0) {
    for (int idx = threadIdx.x; idx < KDIM * 32; idx += TPB) {
        int k = idx >> 5, r = idx & 31;
        int jj = r >> 2, gate = r & 3;
        int rg = r >> 3, i = (r & 7) >> 1, lo = r & 1;
        int rgrow = gate * HID + j0 + jj;
        float v = (k < HID) ? Whh[rgrow * HID + k] : Wih[rgrow * FEAT + (k - HID)];
        w2dup[k * 64 + i * 16 + rg * 4 + lo * 2 + 0] = v;
        w2dup[k * 64 + i * 16 + rg * 4 + lo * 2 + 1] = v;
    }
    if (threadIdx.x < 32) {
        int r = threadIdx.x;
        int jj = r >> 2, gate = r & 3;
        bias_s[r] = bias[gate * HID + j0 + jj];
    }
}

// ---------------- one k contribution: 16 FMA2 against 4 LDS.128 ----------------
template <bool OUT>
__device__ __forceinline__ void kstep(float4 s, ull* acc, ull* o,
                                      const float* wk, const float* wo) {
    ulonglong2 ss = *(const ulonglong2*)&s;
#pragma unroll
    for (int i = 0; i < 4; ++i) {
        ulonglong2 w = *(const ulonglong2*)(wk + i * 16);
        FMA2(acc[4 * i + 0], ss.x, w.x); FMA2(acc[4 * i + 1], ss.y, w.x);
        FMA2(acc[4 * i + 2], ss.x, w.y); FMA2(acc[4 * i + 3], ss.y, w.y);
    }
    if (OUT) {
        ulonglong2 w = *(const ulonglong2*)wo;
        FMA2(o[0], ss.x, w.x); FMA2(o[1], ss.y, w.x);
        FMA2(o[2], ss.x, w.y); FMA2(o[3], ss.y, w.y);
    }
}

// ---------------- h-part GEMM over 32 k (critical path) ----------------
template <bool OUT>
__device__ __forceinline__ void gemm_h(const float* __restrict__ sp,
                                       const float* __restrict__ w2dup_rg,
                                       const float* __restrict__ woutd,
                                       ull* acc, ull* o, int klo) {
    float4 sv[8];
#pragma unroll
    for (int i = 0; i < 8; ++i) sv[i] = ldcg128v(sp + (klo + i) * BATCH);
#pragma unroll
    for (int i = 0; i < 24; ++i) {
        float4 s = sv[i & 7];
        sv[i & 7] = ldcg128v(sp + (klo + 8 + i) * BATCH);
        kstep<OUT>(s, acc, o, w2dup_rg + (klo + i) * 64, woutd + (klo + i) * 4);
    }
#pragma unroll
    for (int i = 24; i < 32; ++i)
        kstep<OUT>(sv[i & 7], acc, o, w2dup_rg + (klo + i) * 64, woutd + (klo + i) * 4);
}

// ---------------- x partials over 8 k (EPI warps, off critical path) ----------------
__device__ __forceinline__ void accum_x8(int t, ull* acc, const float* __restrict__ w2dup,
                                         int we, int qb4, int rg4) {
    const float* xp = g_xT + t * (FEAT * BATCH) + qb4;
    const int kx = we * KXE;
    float4 sv[KXE];
#pragma unroll
    for (int i = 0; i < KXE; ++i) sv[i] = ldcg128v(xp + (kx + i) * BATCH);
#pragma unroll
    for (int i = 0; i < KXE; ++i)
        kstep<false>(sv[i], acc, (ull*)0, w2dup + (HID + kx + i) * 64 + rg4, (const float*)0);
}

// partial store: rows w*32 + rg*8 + rl, batches bq*4..+3
__device__ __forceinline__ void sts_partials(float* buf, const ull* acc, int w, int rg, int bq) {
#pragma unroll
    for (int rl = 0; rl < 8; ++rl) {
        ulonglong2 v; v.x = acc[rl * 2 + 0]; v.y = acc[rl * 2 + 1];
        *(ulonglong2*)(buf + (w * 32 + rg * 8 + rl) * GQ + bq * 4) = v;
    }
}

// ---------------- SMEM layout (floats) ----------------
//  w2dup  20480 @ 0
//  woutd   1024 @ 20480
//  red    16384 @ 21504   (2 parities * 8 slices * 32 rows * 32 b)
//  xred   16384 @ 37888
//  red_o   1024 @ 54272   (2 parities * 2 f * 8 slices * 32 b)
//  c_s      256 @ 55296
//  bias_s    32 @ 55552
#define SMEM_FLOATS 55584
#define SMEM_BYTES  (SMEM_FLOATS * 4)

__global__ void __launch_bounds__(TPB, 1) lstm_persistent_kernel(
    const float* __restrict__ Wih_e, const float* __restrict__ Whh_e, const float* __restrict__ b_e,
    const float* __restrict__ Wih_d, const float* __restrict__ Whh_d, const float* __restrict__ b_d,
    const float* __restrict__ Wout, const float* __restrict__ bout,
    float* __restrict__ out)
{
    extern __shared__ float sm[];
    float* w2dup  = sm;
    float* woutd  = sm + 20480;
    float* red    = sm + 21504;
    float* xred   = sm + 37888;
    float* red_o  = sm + 54272;
    float* c_s    = sm + 55296;
    float* bias_s = sm + 55552;

    const int cta   = blockIdx.x;
    const int tid   = threadIdx.x;
    const int grp   = cta >> 5;
    const int slice = cta & 31;
    const int qb0   = grp * GQ;
    const int j0    = slice * JH;
    const int wid   = tid >> 5;
    const int lane  = tid & 31;
    const int rg    = lane >> 3;
    const int bq    = lane & 7;
    const int rg4   = rg * 4;
    const int qb4   = qb0 + bq * 4;
    const int gbase = grp << 5;
    const bool is_gemm = (wid < 8);
    const int ksr   = (wid + slice) & 7;     // gemm k-rotation
    const int klo   = ksr * KHG;
    const int we    = wid - 8;               // epi warp index

    load_weights(Whh_e, Wih_e, b_e, w2dup, bias_s, j0);
    if (tid < 256) {
        int jj = tid >> 5, b = tid & 31;
        stcg32(&g_S[(j0 + jj) * BATCH + qb0 + b], 0.f);
        c_s[jj * GQ + b] = 0.f;
    }
    __syncthreads();
    if (tid == 0) { __threadfence(); g_flags[cta] = 1u; }

    ull acc[16], o[4];
#pragma unroll
    for (int p = 0; p < 16; ++p) acc[p] = 0ull;
    o[0] = o[1] = o[2] = o[3] = 0ull;

    unsigned step = 1u;
    int cur = 0;

    // epi prefill: x-partials for t=0 into xred[step&1 = 1]
    if (!is_gemm) {
        accum_x8(0, acc, w2dup, we, qb4, rg4);
        sts_partials(xred + (step & 1) * 8192, acc, we, rg, bq);
#pragma unroll
        for (int p = 0; p < 16; ++p) acc[p] = 0ull;
    }

    // ================= encoder =================
    for (int t = 0; t < T_STEPS; ++t) {
        int par = step & 1;
        if (is_gemm) {
            // COALESCED poll: warp 0 watches all 32 group flags with one LDG/iter,
            // then releases GEMM warps via named barrier 3 (256 threads).
            if (wid == 0) {
                while (g_flags[gbase + lane] < step) { }
            }
            asm volatile("bar.sync 3, 256;" ::: "memory");
            __threadfence();
            gemm_h<false>(g_S + cur * SB + qb4, w2dup + rg4, woutd, acc, o, klo);
            sts_partials(red + par * 8192, acc, wid, rg, bq);
            asm volatile("bar.arrive 2, 512;" ::: "memory");
#pragma unroll
            for (int p = 0; p < 16; ++p) acc[p] = 0ull;
        } else {
            asm volatile("bar.sync 2, 512;" ::: "memory");
            int jj = we, b = lane;
            float gi = bias_s[jj * 4 + 0], gf = bias_s[jj * 4 + 1];
            float gg = bias_s[jj * 4 + 2], go = bias_s[jj * 4 + 3];
            const float* rp = red  + par * 8192;
            const float* xp = xred + par * 8192;
#pragma unroll
            for (int q = 0; q < 8; ++q) {
                const float* ba = rp + (q * 32 + jj * 4) * GQ + b;
                gi += ba[0]; gf += ba[GQ]; gg += ba[2 * GQ]; go += ba[3 * GQ];
            }
#pragma unroll
            for (int q = 0; q < 8; ++q) {
                const float* ba = xp + (q * 32 + jj * 4) * GQ + b;
                gi += ba[0]; gf += ba[GQ]; gg += ba[2 * GQ]; go += ba[3 * GQ];
            }
            float c = sigf(gf) * c_s[jj * GQ + b] + sigf(gi) * tanhff(gg);
            c_s[jj * GQ + b] = c;
            stcg32(&g_S[(cur ^ 1) * SB + (j0 + jj) * BATCH + qb0 + b], sigf(go) * tanhff(c));
            asm volatile("bar.sync 1, 256;" ::: "memory");
            if (tid == 256) { __threadfence(); g_flags[cta] = step + 1u; }
            if (t < T_STEPS - 1) {
                accum_x8(t + 1, acc, w2dup, we, qb4, rg4);
                sts_partials(xred + (par ^ 1) * 8192, acc, we, rg, bq);
#pragma unroll
                for (int p = 0; p < 16; ++p) acc[p] = 0ull;
            }
        }
        ++step;
        cur ^= 1;
    }

    // ================= switch to decoder weights =================
    __syncthreads();
    load_weights(Whh_d, Wih_d, b_d, w2dup, bias_s, j0);
    const int f0 = slice * 2;
    for (int k = tid; k < HID; k += TPB) {
        float v0 = Wout[(f0 + 0) * HID + k];
        float v1 = Wout[(f0 + 1) * HID + k];
        woutd[k * 4 + 0] = v0; woutd[k * 4 + 1] = v0;
        woutd[k * 4 + 2] = v1; woutd[k * 4 + 3] = v1;
    }
    float bo0 = bout[f0], bo1 = bout[f0 + 1];
    __syncthreads();

    if (!is_gemm) { // prefill x(t=1023) with decoder weights into xred[step&1]
        accum_x8(T_STEPS - 1, acc, w2dup, we, qb4, rg4);
        sts_partials(xred + (step & 1) * 8192, acc, we, rg, bq);
#pragma unroll
        for (int p = 0; p < 16; ++p) acc[p] = 0ull;
    }

    // ================= decoder (reversed time) =================
    for (int tt = 0; tt < T_STEPS; ++tt) {
        int t = T_STEPS - 1 - tt;
        int par = step & 1;
        if (is_gemm) {
            if (wid == 0) {
                while (g_flags[gbase + lane] < step) { }
            }
            asm volatile("bar.sync 3, 256;" ::: "memory");
            __threadfence();
            gemm_h<true>(g_S + cur * SB + qb4, w2dup + rg4, woutd, acc, o, klo);
            sts_partials(red + par * 8192, acc, wid, rg, bq);
            if (rg == 0) {
                ulonglong2 v0; v0.x = o[0]; v0.y = o[1];
                ulonglong2 v1; v1.x = o[2]; v1.y = o[3];
                *(ulonglong2*)(red_o + par * 512 + wid * GQ + bq * 4) = v0;
                *(ulonglong2*)(red_o + par * 512 + 256 + wid * GQ + bq * 4) = v1;
            }
            asm volatile("bar.arrive 2, 512;" ::: "memory");
#pragma unroll
            for (int p = 0; p < 16; ++p) acc[p] = 0ull;
            o[0] = o[1] = o[2] = o[3] = 0ull;
        } else {
            asm volatile("bar.sync 2, 512;" ::: "memory");
            int jj = we, b = lane;
            float gi = bias_s[jj * 4 + 0], gf = bias_s[jj * 4 + 1];
            float gg = bias_s[jj * 4 + 2], go = bias_s[jj * 4 + 3];
            const float* rp = red  + par * 8192;
            const float* xp = xred + par * 8192;
#pragma unroll
            for (int q = 0; q < 8; ++q) {
                const float* ba = rp + (q * 32 + jj * 4) * GQ + b;
                gi += ba[0]; gf += ba[GQ]; gg += ba[2 * GQ]; go += ba[3 * GQ];
            }
#pragma unroll
            for (int q = 0; q < 8; ++q) {
                const float* ba = xp + (q * 32 + jj * 4) * GQ + b;
                gi += ba[0]; gf += ba[GQ]; gg += ba[2 * GQ]; go += ba[3 * GQ];
            }
            float c = sigf(gf) * c_s[jj * GQ + b] + sigf(gi) * tanhff(gg);
            c_s[jj * GQ + b] = c;
            stcg32(&g_S[(cur ^ 1) * SB + (j0 + jj) * BATCH + qb0 + b], sigf(go) * tanhff(c));
            asm volatile("bar.sync 1, 256;" ::: "memory");
            if (tid == 256) { __threadfence(); g_flags[cta] = step + 1u; }

            if (we == 0) { // output emit for step t (off critical path)
                float s0 = 0.f, s1 = 0.f;
#pragma unroll
                for (int q = 0; q < 8; ++q) {
                    s0 += red_o[par * 512 + q * GQ + b];
                    s1 += red_o[par * 512 + 256 + q * GQ + b];
                }
                float2 res; res.x = s0 + bo0; res.y = s1 + bo1;
                *(float2*)(out + (qb0 + b) * TF + t * FEAT + f0) = res;
            }
            if (tt < T_STEPS - 1) {
                accum_x8(t - 1, acc, w2dup, we, qb4, rg4);
                sts_partials(xred + (par ^ 1) * 8192, acc, we, rg, bq);
#pragma unroll
                for (int p = 0; p < 16; ++p) acc[p] = 0ull;
            }
        }
        ++step;
        cur ^= 1;
    }

    // ---- reset barrier state for graph replays ----
    __syncthreads();
    if (tid == 0) {
        atomicAdd(&g_done, 1u);
        if (cta == 0) {
            while (*((volatile unsigned*)&g_done) < NCTA) { }
            for (int i = 0; i < NCTA; ++i) g_flags[i] = 0u;
            __threadfence();
            g_done = 0u;
        }
    }
}

// ---------------- launch ----------------
extern "C" void kernel_launch(void* const* d_in, const int* in_sizes, int n_in,
                              void* d_out, int out_size) {
    const float* ts    = (const float*)d_in[0];
    const float* Wih_e = (const float*)d_in[1];
    const float* Whh_e = (const float*)d_in[2];
    const float* b_e   = (const float*)d_in[3];
    const float* Wih_d = (const float*)d_in[4];
    const float* Whh_d = (const float*)d_in[5];
    const float* b_d   = (const float*)d_in[6];
    const float* Wout  = (const float*)d_in[7];
    const float* bout  = (const float*)d_in[8];
    float* out = (float*)d_out;

    cudaFuncSetAttribute(lstm_persistent_kernel,
                         cudaFuncAttributeMaxDynamicSharedMemorySize, SMEM_BYTES);

    transpose_x_kernel<<<T_STEPS, 256>>>(ts);
    lstm_persistent_kernel<<<NCTA, TPB, SMEM_BYTES>>>(
        Wih_e, Whh_e, b_e, Wih_d, Whh_d, b_d, Wout, bout, out);
}